// round 1
// baseline (speedup 1.0000x reference)
#include <cuda_runtime.h>
#include <cuda_bf16.h>
#include <cstdint>

// Problem constants (fixed shapes for this problem instance)
constexpr int Bc  = 2;
constexpr int Nc  = 50;    // num preds
constexpr int NG  = 15;    // num gts
constexpr int Cc  = 17;    // channels
constexpr int HWc = 4096;  // 64*64

constexpr int KCHUNK = 1024;          // HW pixels per block (within one channel)
constexpr int KIN    = 128;           // inner smem tile
constexpr int NIT    = KCHUNK / KIN;  // 8
constexpr int IPAD   = 56;            // padded pred rows (8 groups * 7)
constexpr int JPAD   = 16;            // padded gt rows (2 groups * 8)
constexpr int THREADS = 512;          // 16 warps: 8 i-groups x 2 j-groups

constexpr int SMEM_FLOATS = (3 * IPAD + 3 * JPAD) * KIN;  // 216*128
constexpr size_t SMEM_BYTES = SMEM_FLOATS * sizeof(float);

// Device-global scratch (no allocations allowed)
__device__ float g_acc[Bc * Nc * NG];
__device__ float g_kp[Bc * NG];
__device__ int   g_mask[Bc * NG * Cc];   // 1 = channel has keypoints

// ---------------------------------------------------------------------------
// Kernel 0: zero accumulators
// ---------------------------------------------------------------------------
__global__ void zero_kernel() {
    int t = threadIdx.x;
    for (int i = t; i < Bc * Nc * NG; i += blockDim.x) g_acc[i] = 0.0f;
    for (int i = t; i < Bc * NG; i += blockDim.x)      g_kp[i]  = 0.0f;
}

// ---------------------------------------------------------------------------
// Kernel 1: per (b, j, c) channel sum of gt heatmap -> mask + num_kp count
// grid (Cc, NG, Bc), block 128
// ---------------------------------------------------------------------------
__global__ void mask_kernel(const float* __restrict__ gh) {
    int c = blockIdx.x, j = blockIdx.y, b = blockIdx.z;
    const float* base = gh + ((size_t)((b * NG + j) * Cc + c)) * HWc;
    int tid = threadIdx.x;
    float s = 0.0f;
    // 4096 / 128 = 32 per thread, vectorized
    const float4* b4 = reinterpret_cast<const float4*>(base);
    for (int k = tid; k < HWc / 4; k += 128) {
        float4 v = b4[k];
        s += v.x + v.y + v.z + v.w;
    }
    // warp reduce
    for (int off = 16; off; off >>= 1) s += __shfl_xor_sync(0xffffffffu, s, off);
    __shared__ float ws[4];
    if ((tid & 31) == 0) ws[tid >> 5] = s;
    __syncthreads();
    if (tid == 0) {
        float total = ws[0] + ws[1] + ws[2] + ws[3];
        int valid = (total > 0.0f) ? 1 : 0;   // gt heatmaps are nonnegative
        g_mask[(b * NG + j) * Cc + c] = valid;
        if (valid) atomicAdd(&g_kp[b * NG + j], 1.0f);
    }
}

// ---------------------------------------------------------------------------
// Kernel 2: fused transform + 3-component GEMM over K = C*HW
// grid (HW/KCHUNK=4, Cc=17, Bc=2) = 136 blocks, block = 512
// ---------------------------------------------------------------------------
__global__ __launch_bounds__(THREADS, 1)
void gemm_kernel(const float* __restrict__ ph, const float* __restrict__ gh) {
    extern __shared__ float sm[];
    float* sA = sm;                       // [IPAD][KIN]
    float* sB = sA + IPAD * KIN;
    float* sC = sB + IPAD * KIN;
    float* sU = sC + IPAD * KIN;          // [JPAD][KIN]
    float* sV = sU + JPAD * KIN;
    float* sW = sV + JPAD * KIN;

    const int b = blockIdx.z, c = blockIdx.y;
    const int k0 = blockIdx.x * KCHUNK;

    const int tid  = threadIdx.x;
    const int lane = tid & 31;
    const int w    = tid >> 5;      // 0..15
    const int ig   = w >> 1;        // 0..7
    const int jg   = w & 1;         // 0..1
    const int i_base = ig * 7;
    const int j_base = jg * 8;

    const float* phb = ph + ((size_t)(b * Nc * Cc + c)) * HWc;   // + i*Cc*HWc
    const float* ghb = gh + ((size_t)(b * NG * Cc + c)) * HWc;   // + j*Cc*HWc

    float acc[7][8];
#pragma unroll
    for (int ii = 0; ii < 7; ii++)
#pragma unroll
        for (int jj = 0; jj < 8; jj++) acc[ii][jj] = 0.0f;

    for (int t = 0; t < NIT; ++t) {
        const int kbase = k0 + t * KIN;

        // ---- stage pred transforms: A = sp*p^2, B = x*p^2, C = (sp-x)*(1-p)^2
        for (int idx = tid; idx < IPAD * KIN; idx += THREADS) {
            int i  = idx >> 7;            // KIN = 128
            int kk = idx & (KIN - 1);
            float Av = 0.f, Bv = 0.f, Cv = 0.f;
            if (i < Nc) {
                float x = phb[(size_t)i * Cc * HWc + kbase + kk];
                float e = __expf(-fabsf(x));
                float l = __logf(1.0f + e);
                float r = __fdividef(1.0f, 1.0f + e);
                float p   = (x >= 0.f) ? r : e * r;       // sigmoid(x)
                float omp = (x >= 0.f) ? e * r : r;       // 1 - sigmoid(x)
                float sp   = fmaxf(x, 0.f) + l;           // softplus(x)
                float spmx = fmaxf(-x, 0.f) + l;          // softplus(x) - x
                float p2 = p * p;
                Av = sp * p2;
                Bv = x * p2;
                Cv = spmx * omp * omp;
            }
            sA[idx] = Av; sB[idx] = Bv; sC[idx] = Cv;
        }
        // ---- stage gt transforms: u=(1-t)^4, v=t*u, w=(t==1), masked channels -> 0
        for (int idx = tid; idx < JPAD * KIN; idx += THREADS) {
            int j  = idx >> 7;
            int kk = idx & (KIN - 1);
            float u = 0.f, v = 0.f, wv = 0.f;
            if (j < NG && g_mask[(b * NG + j) * Cc + c]) {
                float tt = ghb[(size_t)j * Cc * HWc + kbase + kk];
                if (tt == 1.0f) {
                    wv = 1.0f;
                } else {
                    float o  = 1.0f - tt;
                    float o2 = o * o;
                    u = o2 * o2;
                    v = tt * u;
                }
            }
            sU[idx] = u; sV[idx] = v; sW[idx] = wv;
        }
        __syncthreads();

        // ---- register-tiled GEMM: 7 i x 8 j per warp, lanes split k
#pragma unroll
        for (int s = 0; s < KIN / 32; ++s) {
            const int kk = lane + 32 * s;
            float uj[8], vj[8], wj[8];
#pragma unroll
            for (int jj = 0; jj < 8; jj++) {
                int j = j_base + jj;
                uj[jj] = sU[j * KIN + kk];
                vj[jj] = sV[j * KIN + kk];
                wj[jj] = sW[j * KIN + kk];
            }
#pragma unroll
            for (int ii = 0; ii < 7; ii++) {
                int i = i_base + ii;
                float a  = sA[i * KIN + kk];
                float nb = -sB[i * KIN + kk];
#pragma unroll
                for (int jj = 0; jj < 8; jj++) {
                    acc[ii][jj] = fmaf(a, uj[jj], acc[ii][jj]);
                    acc[ii][jj] = fmaf(nb, vj[jj], acc[ii][jj]);
                }
            }
            // w-term: t==1 pixels essentially never occur -> skip when all zero
            float wsum = 0.f;
#pragma unroll
            for (int jj = 0; jj < 8; jj++) wsum += wj[jj];
            if (wsum != 0.f) {
#pragma unroll
                for (int ii = 0; ii < 7; ii++) {
                    int i = i_base + ii;
                    float cc = sC[i * KIN + kk];
#pragma unroll
                    for (int jj = 0; jj < 8; jj++)
                        acc[ii][jj] = fmaf(cc, wj[jj], acc[ii][jj]);
                }
            }
        }
        __syncthreads();
    }

    // ---- warp-reduce over lanes, atomic accumulate
#pragma unroll
    for (int ii = 0; ii < 7; ii++) {
#pragma unroll
        for (int jj = 0; jj < 8; jj++) {
            float v = acc[ii][jj];
#pragma unroll
            for (int off = 16; off; off >>= 1)
                v += __shfl_xor_sync(0xffffffffu, v, off);
            if (lane == 0) {
                int i = i_base + ii, j = j_base + jj;
                if (i < Nc && j < NG)
                    atomicAdd(&g_acc[(b * Nc + i) * NG + j], v);
            }
        }
    }
}

// ---------------------------------------------------------------------------
// Kernel 3: finalize — score cost + offset cost + combine
// grid (Bc), block Nc*NG = 750
// ---------------------------------------------------------------------------
__global__ void finalize_kernel(const float* __restrict__ ps,
                                const float* __restrict__ po,
                                const float* __restrict__ go,
                                float* __restrict__ out) {
    int b = blockIdx.x;
    int tid = threadIdx.x;           // 0..749
    int i = tid / NG;
    int j = tid % NG;

    float num_kp = fmaxf(g_kp[b * NG + j], 1.0f);

    // score cost: 0.25 * softplus(-s) * sigmoid(-s)^2  (broadcast over j)
    float sv = ps[b * Nc + i];
    float e = __expf(-fabsf(sv));
    float l = __logf(1.0f + e);
    float r = __fdividef(1.0f, 1.0f + e);
    float sig_neg = (sv >= 0.f) ? e * r : r;          // 1 - sigmoid(s)
    float sp_neg  = fmaxf(-sv, 0.f) + l;              // softplus(-s)
    float score_cost = 0.25f * sp_neg * sig_neg * sig_neg;

    // offset cost
    float osum = 0.0f;
    for (int c = 0; c < Cc; c++) {
        if (!g_mask[(b * NG + j) * Cc + c]) continue;
        const float* pp = po + ((size_t)((b * Nc + i) * Cc + c)) * 2;
        const float* gp = go + ((size_t)((b * NG + j) * Cc + c)) * 2;
        float x0 = pp[0], x1 = pp[1];
        float s0 = __fdividef(1.0f, 1.0f + __expf(-x0));
        float s1 = __fdividef(1.0f, 1.0f + __expf(-x1));
        float d0 = s0 - gp[0];
        float d1 = s1 - gp[1];
        osum += d0 * d0 + d1 * d1;
    }
    float off_cost = osum / num_kp * 0.5f;

    float hm_cost = g_acc[(b * Nc + i) * NG + j] / num_kp;

    out[(b * Nc + i) * NG + j] = 2.0f * hm_cost + score_cost + off_cost;
}

// ---------------------------------------------------------------------------
extern "C" void kernel_launch(void* const* d_in, const int* in_sizes, int n_in,
                              void* d_out, int out_size) {
    const float* ph = (const float*)d_in[0];  // pred_hms     [B,N,C,H,W]
    const float* ps = (const float*)d_in[1];  // pred_scores  [B,N,1]
    const float* po = (const float*)d_in[2];  // pred_offsets [B,N,C,2]
    const float* gh = (const float*)d_in[3];  // gt_heatmaps  [B,n,C,H,W]
    const float* go = (const float*)d_in[4];  // gt_offsets   [B,n,C,2]
    float* out = (float*)d_out;

    cudaFuncSetAttribute(gemm_kernel,
                         cudaFuncAttributeMaxDynamicSharedMemorySize,
                         (int)SMEM_BYTES);

    zero_kernel<<<1, 256>>>();
    mask_kernel<<<dim3(Cc, NG, Bc), 128>>>(gh);
    gemm_kernel<<<dim3(HWc / KCHUNK, Cc, Bc), THREADS, SMEM_BYTES>>>(ph, gh);
    finalize_kernel<<<Bc, Nc * NG>>>(ps, po, go, out);
}

// round 4
// speedup vs baseline: 1.0014x; 1.0014x over previous
#include <cuda_runtime.h>
#include <cuda_bf16.h>
#include <cstdint>

// Problem constants
constexpr int Bc  = 2;
constexpr int Nc  = 50;
constexpr int NG  = 15;
constexpr int Cc  = 17;
constexpr int HWc = 4096;

constexpr int KCHUNK = 1024;
constexpr int KIN    = 128;
constexpr int NIT    = KCHUNK / KIN;   // 8
constexpr int JPAD   = 16;
constexpr int THREADS = 512;           // 16 warps: 2 i-groups x 8 j-groups

constexpr int SMEM_FLOATS = (3 * Nc + 3 * JPAD) * KIN;   // 198*128
constexpr size_t SMEM_BYTES = SMEM_FLOATS * sizeof(float);

__device__ float g_acc[Bc * Nc * NG];
__device__ int   g_mask[Bc * NG * Cc];

#define FMA_F32X2(d, a, b, c) \
    asm("fma.rn.f32x2 %0, %1, %2, %3;" : "=l"(d) : "l"(a), "l"(b), "l"(c))

// ---------------------------------------------------------------------------
// Kernel 1: channel mask from gt heatmap sums  (+ zero g_acc, folded in)
// grid (Cc, NG, Bc), block 128
// ---------------------------------------------------------------------------
__global__ void mask_kernel(const float* __restrict__ gh) {
    int c = blockIdx.x, j = blockIdx.y, b = blockIdx.z;
    int flat = (b * NG + j) * Cc + c;            // 0..509
    int tid = threadIdx.x;

    // fold: zero g_acc (gemm runs in a later launch, so no race; 510 blocks
    // each zero a disjoint strided slice)
    for (int z = flat + tid * (Bc * NG * Cc); z < Bc * Nc * NG;
         z += 128 * Bc * NG * Cc)
        g_acc[z] = 0.0f;

    const float* base = gh + ((size_t)flat) * HWc;
    float s = 0.0f;
    const float4* b4 = reinterpret_cast<const float4*>(base);
    for (int k = tid; k < HWc / 4; k += 128) {
        float4 v = b4[k];
        s += v.x + v.y + v.z + v.w;
    }
    for (int off = 16; off; off >>= 1) s += __shfl_xor_sync(0xffffffffu, s, off);
    __shared__ float ws[4];
    if ((tid & 31) == 0) ws[tid >> 5] = s;
    __syncthreads();
    if (tid == 0) {
        float total = ws[0] + ws[1] + ws[2] + ws[3];
        g_mask[flat] = (total > 0.0f) ? 1 : 0;
    }
}

// ---------------------------------------------------------------------------
// Kernel 2: fused transform + 3-term GEMM, packed f32x2 FMA
// grid (HW/KCHUNK=4, Cc, Bc) = 136 blocks, block = 512
// warp w: ig = w>>3 (0..1) -> 25 i rows; jg = w&7 (0..7) -> 2 j rows
// ---------------------------------------------------------------------------
__global__ __launch_bounds__(THREADS, 1)
void gemm_kernel(const float* __restrict__ ph, const float* __restrict__ gh) {
    extern __shared__ float sm[];
    float* sA = sm;                     // [Nc][KIN]   sp*p^2
    float* sB = sA + Nc * KIN;          // [Nc][KIN]   -(x*p^2)
    float* sC = sB + Nc * KIN;          // [Nc][KIN]   (sp-x)*(1-p)^2
    float* sU = sC + Nc * KIN;          // [JPAD][KIN] (1-t)^4
    float* sV = sU + JPAD * KIN;        // [JPAD][KIN] t*(1-t)^4
    float* sW = sV + JPAD * KIN;        // [JPAD][KIN] (t==1)
    __shared__ int sMask[JPAD];

    const int b = blockIdx.z, c = blockIdx.y;
    const int k0 = blockIdx.x * KCHUNK;

    const int tid  = threadIdx.x;
    const int lane = tid & 31;
    const int w    = tid >> 5;
    const int ig   = w >> 3;            // 0..1
    const int jg   = w & 7;             // 0..7
    const int i_base = ig * 25;
    const int j_base = jg * 2;

    if (tid < JPAD)
        sMask[tid] = (tid < NG) ? g_mask[(b * NG + tid) * Cc + c] : 0;

    const float* phb = ph + ((size_t)(b * Nc * Cc + c)) * HWc;
    const float* ghb = gh + ((size_t)(b * NG * Cc + c)) * HWc;

    unsigned long long acc[25][2];
#pragma unroll
    for (int ii = 0; ii < 25; ii++) { acc[ii][0] = 0ull; acc[ii][1] = 0ull; }

    __syncthreads();   // sMask visible

    for (int t = 0; t < NIT; ++t) {
        const int kbase = k0 + t * KIN;

        // ---- stage pred transforms (vectorized float4)
        for (int idx = tid; idx < Nc * (KIN / 4); idx += THREADS) {
            int i   = idx >> 5;                    // 32 float4 per row
            int kk4 = (idx & 31) << 2;
            float4 x4 = *reinterpret_cast<const float4*>(
                &phb[(size_t)i * Cc * HWc + kbase + kk4]);
            float4 a4, b4o, c4;
            float* xs = &x4.x; float* as = &a4.x; float* bs = &b4o.x; float* cs = &c4.x;
#pragma unroll
            for (int q = 0; q < 4; q++) {
                float x = xs[q];
                float e = __expf(-fabsf(x));
                float l = __logf(1.0f + e);
                float r = __fdividef(1.0f, 1.0f + e);
                float p   = (x >= 0.f) ? r : e * r;
                float omp = (x >= 0.f) ? e * r : r;
                float sp   = fmaxf(x, 0.f) + l;
                float spmx = fmaxf(-x, 0.f) + l;
                float p2 = p * p;
                as[q] = sp * p2;
                bs[q] = -(x * p2);
                cs[q] = spmx * omp * omp;
            }
            int so = i * KIN + kk4;
            *reinterpret_cast<float4*>(&sA[so]) = a4;
            *reinterpret_cast<float4*>(&sB[so]) = b4o;
            *reinterpret_cast<float4*>(&sC[so]) = c4;
        }
        // ---- stage gt transforms (one float4 per thread)
        {
            int idx = tid;                         // 512 = 16*32 float4
            int j   = idx >> 5;
            int kk4 = (idx & 31) << 2;
            float4 u4 = {0,0,0,0}, v4 = {0,0,0,0}, w4 = {0,0,0,0};
            if (j < NG && sMask[j]) {
                float4 t4 = *reinterpret_cast<const float4*>(
                    &ghb[(size_t)j * Cc * HWc + kbase + kk4]);
                float* ts = &t4.x; float* us = &u4.x; float* vs = &v4.x; float* wsp = &w4.x;
#pragma unroll
                for (int q = 0; q < 4; q++) {
                    float tt = ts[q];
                    if (tt == 1.0f) { wsp[q] = 1.0f; }
                    else {
                        float o  = 1.0f - tt;
                        float o2 = o * o;
                        float u  = o2 * o2;
                        us[q] = u; vs[q] = tt * u;
                    }
                }
            }
            int so = j * KIN + kk4;
            *reinterpret_cast<float4*>(&sU[so]) = u4;
            *reinterpret_cast<float4*>(&sV[so]) = v4;
            *reinterpret_cast<float4*>(&sW[so]) = w4;
        }
        __syncthreads();

        // ---- packed-f32x2 GEMM: 25 i x 2 j per warp, lane covers 2 k
#pragma unroll
        for (int s = 0; s < 2; ++s) {
            const int kk = 2 * lane + 64 * s;
            const int j0 = j_base * KIN + kk;
            const int j1 = (j_base + 1) * KIN + kk;
            unsigned long long u0 = *reinterpret_cast<unsigned long long*>(&sU[j0]);
            unsigned long long u1 = *reinterpret_cast<unsigned long long*>(&sU[j1]);
            unsigned long long v0 = *reinterpret_cast<unsigned long long*>(&sV[j0]);
            unsigned long long v1 = *reinterpret_cast<unsigned long long*>(&sV[j1]);
            unsigned long long w0 = *reinterpret_cast<unsigned long long*>(&sW[j0]);
            unsigned long long w1 = *reinterpret_cast<unsigned long long*>(&sW[j1]);

#pragma unroll
            for (int ii = 0; ii < 25; ii++) {
                int io = (i_base + ii) * KIN + kk;
                unsigned long long a2 = *reinterpret_cast<unsigned long long*>(&sA[io]);
                unsigned long long b2 = *reinterpret_cast<unsigned long long*>(&sB[io]);
                FMA_F32X2(acc[ii][0], a2, u0, acc[ii][0]);
                FMA_F32X2(acc[ii][1], a2, u1, acc[ii][1]);
                FMA_F32X2(acc[ii][0], b2, v0, acc[ii][0]);
                FMA_F32X2(acc[ii][1], b2, v1, acc[ii][1]);
            }
            // rare t==1 path (exactness); warp-uniform skip
            if (__any_sync(0xffffffffu, (w0 | w1) != 0ull)) {
#pragma unroll
                for (int ii = 0; ii < 25; ii++) {
                    int io = (i_base + ii) * KIN + kk;
                    unsigned long long c2 = *reinterpret_cast<unsigned long long*>(&sC[io]);
                    FMA_F32X2(acc[ii][0], c2, w0, acc[ii][0]);
                    FMA_F32X2(acc[ii][1], c2, w1, acc[ii][1]);
                }
            }
        }
        __syncthreads();
    }

    // ---- reduce packed halves + lanes, accumulate to global
#pragma unroll
    for (int ii = 0; ii < 25; ii++) {
#pragma unroll
        for (int jj = 0; jj < 2; jj++) {
            unsigned long long a = acc[ii][jj];
            float v = __uint_as_float((unsigned)(a & 0xffffffffu)) +
                      __uint_as_float((unsigned)(a >> 32));
#pragma unroll
            for (int off = 16; off; off >>= 1)
                v += __shfl_xor_sync(0xffffffffu, v, off);
            if (lane == 0) {
                int i = i_base + ii, j = j_base + jj;
                if (j < NG)
                    atomicAdd(&g_acc[(b * Nc + i) * NG + j], v);
            }
        }
    }
}

// ---------------------------------------------------------------------------
// Kernel 3: finalize — grid (Nc, Bc) = 100 blocks, block 256
// ---------------------------------------------------------------------------
__global__ void finalize_kernel(const float* __restrict__ ps,
                                const float* __restrict__ po,
                                const float* __restrict__ go,
                                float* __restrict__ out) {
    int i = blockIdx.x, b = blockIdx.y;
    int tid = threadIdx.x;

    __shared__ float s_off[NG];
    __shared__ float s_kp[NG];
    __shared__ float s_score;

    if (tid < NG) { s_off[tid] = 0.0f; s_kp[tid] = 0.0f; }
    if (tid == 0) {
        float sv = ps[b * Nc + i];
        float e = __expf(-fabsf(sv));
        float l = __logf(1.0f + e);
        float r = __fdividef(1.0f, 1.0f + e);
        float sig_neg = (sv >= 0.f) ? e * r : r;
        float sp_neg  = fmaxf(-sv, 0.f) + l;
        s_score = 0.25f * sp_neg * sig_neg * sig_neg;
    }
    __syncthreads();

    if (tid < NG * Cc) {                 // 255 threads: (j, c)
        int j = tid / Cc, c = tid % Cc;
        int m = g_mask[(b * NG + j) * Cc + c];
        atomicAdd(&s_kp[j], (float)m);
        if (m) {
            const float* pp = po + ((size_t)((b * Nc + i) * Cc + c)) * 2;
            const float* gp = go + ((size_t)((b * NG + j) * Cc + c)) * 2;
            float s0 = __fdividef(1.0f, 1.0f + __expf(-pp[0]));
            float s1 = __fdividef(1.0f, 1.0f + __expf(-pp[1]));
            float d0 = s0 - gp[0], d1 = s1 - gp[1];
            atomicAdd(&s_off[j], d0 * d0 + d1 * d1);
        }
    }
    __syncthreads();

    if (tid < NG) {
        int j = tid;
        float kp = fmaxf(s_kp[j], 1.0f);
        float hm = g_acc[(b * Nc + i) * NG + j] / kp;
        out[(b * Nc + i) * NG + j] = 2.0f * hm + s_score + s_off[j] / kp * 0.5f;
    }
}

// ---------------------------------------------------------------------------
extern "C" void kernel_launch(void* const* d_in, const int* in_sizes, int n_in,
                              void* d_out, int out_size) {
    const float* ph = (const float*)d_in[0];
    const float* ps = (const float*)d_in[1];
    const float* po = (const float*)d_in[2];
    const float* gh = (const float*)d_in[3];
    const float* go = (const float*)d_in[4];
    float* out = (float*)d_out;

    cudaFuncSetAttribute(gemm_kernel,
                         cudaFuncAttributeMaxDynamicSharedMemorySize,
                         (int)SMEM_BYTES);

    mask_kernel<<<dim3(Cc, NG, Bc), 128>>>(gh);
    gemm_kernel<<<dim3(HWc / KCHUNK, Cc, Bc), THREADS, SMEM_BYTES>>>(ph, gh);
    finalize_kernel<<<dim3(Nc, Bc), 256>>>(ps, po, go, out);
}

// round 5
// speedup vs baseline: 1.5442x; 1.5421x over previous
#include <cuda_runtime.h>
#include <cuda_bf16.h>
#include <cstdint>

// Problem constants
constexpr int Bc  = 2;
constexpr int Nc  = 50;
constexpr int NG  = 15;
constexpr int Cc  = 17;
constexpr int HWc = 4096;

constexpr int KCHUNK = 1024;
constexpr int KIN    = 128;
constexpr int NIT    = KCHUNK / KIN;   // 8
constexpr int IPAD   = 64;             // padded pred rows (16 warps * 4)
constexpr int JPAD   = 16;
constexpr int THREADS = 512;

constexpr int SMEM_FLOATS = (3 * IPAD + 3 * JPAD) * KIN;   // 240*128
constexpr size_t SMEM_BYTES = SMEM_FLOATS * sizeof(float); // 120 KB

__device__ float g_acc[Bc * Nc * NG];
__device__ int   g_mask[Bc * NG * Cc];

#define FMA_F32X2(d, a, b, c) \
    asm("fma.rn.f32x2 %0, %1, %2, %3;" : "=l"(d) : "l"(a), "l"(b), "l"(c))

// ---------------------------------------------------------------------------
// Kernel 1: channel mask (early-exit: values nonneg => sum>0 iff any>0)
//           + fold in zeroing of g_acc
// grid (Cc, NG, Bc), block 128
// ---------------------------------------------------------------------------
__global__ void mask_kernel(const float* __restrict__ gh) {
    int c = blockIdx.x, j = blockIdx.y, b = blockIdx.z;
    int flat = (b * NG + j) * Cc + c;            // 0..509
    int tid = threadIdx.x;

    // zero g_acc: 510 blocks each clear a disjoint strided slice
    for (int z = flat + tid * (Bc * NG * Cc); z < Bc * Nc * NG;
         z += 128 * Bc * NG * Cc)
        g_acc[z] = 0.0f;

    const float4* b4 = reinterpret_cast<const float4*>(gh + ((size_t)flat) * HWc);
    int found = 0;
    for (int stripe = 0; stripe < HWc / 4 / 128; ++stripe) {   // 8 stripes
        float4 v = b4[stripe * 128 + tid];
        int has = (v.x > 0.f) | (v.y > 0.f) | (v.z > 0.f) | (v.w > 0.f);
        found = __syncthreads_or(has);
        if (found) break;                 // uniform across block
    }
    if (tid == 0) g_mask[flat] = found;
}

// ---------------------------------------------------------------------------
// Kernel 2: fused transform + 3-term GEMM, packed f32x2, half-warp j-split
// grid (HW/KCHUNK=4, Cc, Bc) = 136 blocks, block = 512 (16 warps)
// warp w: i rows [4w, 4w+4); lanes 0-15 -> j 0..7, lanes 16-31 -> j 8..15
// lane covers packed k-pair {2*lk, 2*lk+1} + 32*s
// ---------------------------------------------------------------------------
__global__ __launch_bounds__(THREADS, 1)
void gemm_kernel(const float* __restrict__ ph, const float* __restrict__ gh) {
    extern __shared__ float sm[];
    float* sA = sm;                      // [IPAD][KIN]  sp*p^2
    float* sB = sA + IPAD * KIN;         // [IPAD][KIN]  -(x*p^2)
    float* sC = sB + IPAD * KIN;         // [IPAD][KIN]  (sp-x)*(1-p)^2
    float* sU = sC + IPAD * KIN;         // [JPAD][KIN]  (1-t)^4
    float* sV = sU + JPAD * KIN;         // [JPAD][KIN]  t*(1-t)^4
    float* sW = sV + JPAD * KIN;         // [JPAD][KIN]  (t==1)
    __shared__ int sMask[JPAD];

    const int b = blockIdx.z, c = blockIdx.y;
    const int k0 = blockIdx.x * KCHUNK;

    const int tid  = threadIdx.x;
    const int lane = tid & 31;
    const int wrp  = tid >> 5;           // 0..15
    const int lk   = lane & 15;          // 0..15 (k sublane)
    const int half = lane >> 4;          // 0/1   (j half)
    const int i_base = wrp * 4;
    const int j_base = half * 8;

    // zero pad rows [Nc, IPAD) once (never rewritten)
    for (int idx = tid; idx < (IPAD - Nc) * KIN; idx += THREADS) {
        sA[Nc * KIN + idx] = 0.f;
        sB[Nc * KIN + idx] = 0.f;
        sC[Nc * KIN + idx] = 0.f;
    }
    if (tid < JPAD)
        sMask[tid] = (tid < NG) ? g_mask[(b * NG + tid) * Cc + c] : 0;

    const float* phb = ph + ((size_t)(b * Nc * Cc + c)) * HWc;
    const float* ghb = gh + ((size_t)(b * NG * Cc + c)) * HWc;

    unsigned long long acc[4][8];
#pragma unroll
    for (int ii = 0; ii < 4; ii++)
#pragma unroll
        for (int jj = 0; jj < 8; jj++) acc[ii][jj] = 0ull;

    __syncthreads();   // sMask + pad zeros visible

    // per-thread staging coordinates
    const int gj   = tid >> 5;                 // gh row 0..15
    const int gkk4 = (tid & 31) << 2;

    // ---- prefetch tile 0
    float4 xr[4];
    float4 gr = make_float4(0.f, 0.f, 0.f, 0.f);
    {
        const int kbase = k0;
#pragma unroll
        for (int q = 0; q < 4; q++) {
            int idx = tid + q * THREADS;
            if (idx < Nc * (KIN / 4)) {
                int i = idx >> 5, kk4 = (idx & 31) << 2;
                xr[q] = *reinterpret_cast<const float4*>(
                    &phb[(size_t)i * Cc * HWc + kbase + kk4]);
            }
        }
        if (gj < NG)
            gr = *reinterpret_cast<const float4*>(
                &ghb[(size_t)gj * Cc * HWc + kbase + gkk4]);
    }

    for (int t = 0; t < NIT; ++t) {
        // ---- transform & store current tile from registers
        int myW = 0;
#pragma unroll
        for (int q = 0; q < 4; q++) {
            int idx = tid + q * THREADS;
            if (idx < Nc * (KIN / 4)) {
                int i = idx >> 5, kk4 = (idx & 31) << 2;
                float4 a4, b4o, c4;
                float* xs = &xr[q].x; float* as = &a4.x;
                float* bs = &b4o.x;  float* cs = &c4.x;
#pragma unroll
                for (int qq = 0; qq < 4; qq++) {
                    float x = xs[qq];
                    float e = __expf(-fabsf(x));
                    float l = __logf(1.0f + e);
                    float r = __fdividef(1.0f, 1.0f + e);
                    float p   = (x >= 0.f) ? r : e * r;
                    float omp = (x >= 0.f) ? e * r : r;
                    float sp   = fmaxf(x, 0.f) + l;
                    float spmx = fmaxf(-x, 0.f) + l;
                    float p2 = p * p;
                    as[qq] = sp * p2;
                    bs[qq] = -(x * p2);
                    cs[qq] = spmx * omp * omp;
                }
                int so = i * KIN + kk4;
                *reinterpret_cast<float4*>(&sA[so]) = a4;
                *reinterpret_cast<float4*>(&sB[so]) = b4o;
                *reinterpret_cast<float4*>(&sC[so]) = c4;
            }
        }
        {
            float4 u4 = {0,0,0,0}, v4 = {0,0,0,0}, w4 = {0,0,0,0};
            if (gj < NG && sMask[gj]) {
                float* ts = &gr.x; float* us = &u4.x;
                float* vs = &v4.x; float* wsp = &w4.x;
#pragma unroll
                for (int qq = 0; qq < 4; qq++) {
                    float tt = ts[qq];
                    if (tt == 1.0f) { wsp[qq] = 1.0f; myW = 1; }
                    else {
                        float o  = 1.0f - tt;
                        float o2 = o * o;
                        float u  = o2 * o2;
                        us[qq] = u; vs[qq] = tt * u;
                    }
                }
            }
            int so = gj * KIN + gkk4;
            *reinterpret_cast<float4*>(&sU[so]) = u4;
            *reinterpret_cast<float4*>(&sV[so]) = v4;
            *reinterpret_cast<float4*>(&sW[so]) = w4;
        }

        const int hasW = __syncthreads_or(myW);   // barrier + tile-level w flag

        // ---- prefetch next tile (lands during FMA phase)
        if (t + 1 < NIT) {
            const int kbase = k0 + (t + 1) * KIN;
#pragma unroll
            for (int q = 0; q < 4; q++) {
                int idx = tid + q * THREADS;
                if (idx < Nc * (KIN / 4)) {
                    int i = idx >> 5, kk4 = (idx & 31) << 2;
                    xr[q] = *reinterpret_cast<const float4*>(
                        &phb[(size_t)i * Cc * HWc + kbase + kk4]);
                }
            }
            if (gj < NG)
                gr = *reinterpret_cast<const float4*>(
                    &ghb[(size_t)gj * Cc * HWc + kbase + gkk4]);
        }

        // ---- packed-f32x2 GEMM
#pragma unroll
        for (int s = 0; s < KIN / 32; ++s) {      // 4 s-steps
            const int kk = 2 * lk + 32 * s;
            unsigned long long uj[8], vj[8];
#pragma unroll
            for (int jj = 0; jj < 8; jj++) {
                int jo = (j_base + jj) * KIN + kk;
                uj[jj] = *reinterpret_cast<unsigned long long*>(&sU[jo]);
                vj[jj] = *reinterpret_cast<unsigned long long*>(&sV[jo]);
            }
#pragma unroll
            for (int ii = 0; ii < 4; ii++) {
                int io = (i_base + ii) * KIN + kk;
                unsigned long long a2 = *reinterpret_cast<unsigned long long*>(&sA[io]);
                unsigned long long b2 = *reinterpret_cast<unsigned long long*>(&sB[io]);
#pragma unroll
                for (int jj = 0; jj < 8; jj++) {
                    FMA_F32X2(acc[ii][jj], a2, uj[jj], acc[ii][jj]);
                    FMA_F32X2(acc[ii][jj], b2, vj[jj], acc[ii][jj]);
                }
            }
            if (hasW) {                            // t==1 pixels: essentially never
                unsigned long long wj[8];
#pragma unroll
                for (int jj = 0; jj < 8; jj++)
                    wj[jj] = *reinterpret_cast<unsigned long long*>(
                        &sW[(j_base + jj) * KIN + kk]);
#pragma unroll
                for (int ii = 0; ii < 4; ii++) {
                    int io = (i_base + ii) * KIN + kk;
                    unsigned long long c2 =
                        *reinterpret_cast<unsigned long long*>(&sC[io]);
#pragma unroll
                    for (int jj = 0; jj < 8; jj++)
                        FMA_F32X2(acc[ii][jj], c2, wj[jj], acc[ii][jj]);
                }
            }
        }
        __syncthreads();   // protect smem overwrite next iter
    }

    // ---- reduce: packed halves + 16 k-sublanes (shfl within half-warp)
#pragma unroll
    for (int ii = 0; ii < 4; ii++) {
#pragma unroll
        for (int jj = 0; jj < 8; jj++) {
            unsigned long long a = acc[ii][jj];
            float v = __uint_as_float((unsigned)(a & 0xffffffffu)) +
                      __uint_as_float((unsigned)(a >> 32));
#pragma unroll
            for (int off = 8; off; off >>= 1)
                v += __shfl_xor_sync(0xffffffffu, v, off);
            if (lk == 0) {
                int i = i_base + ii, j = j_base + jj;
                if (i < Nc && j < NG)
                    atomicAdd(&g_acc[(b * Nc + i) * NG + j], v);
            }
        }
    }
}

// ---------------------------------------------------------------------------
// Kernel 3: finalize — grid (Nc, Bc) = 100 blocks, block 256
// ---------------------------------------------------------------------------
__global__ void finalize_kernel(const float* __restrict__ ps,
                                const float* __restrict__ po,
                                const float* __restrict__ go,
                                float* __restrict__ out) {
    int i = blockIdx.x, b = blockIdx.y;
    int tid = threadIdx.x;

    __shared__ float s_off[NG];
    __shared__ float s_kp[NG];
    __shared__ float s_score;

    if (tid < NG) { s_off[tid] = 0.0f; s_kp[tid] = 0.0f; }
    if (tid == 0) {
        float sv = ps[b * Nc + i];
        float e = __expf(-fabsf(sv));
        float l = __logf(1.0f + e);
        float r = __fdividef(1.0f, 1.0f + e);
        float sig_neg = (sv >= 0.f) ? e * r : r;
        float sp_neg  = fmaxf(-sv, 0.f) + l;
        s_score = 0.25f * sp_neg * sig_neg * sig_neg;
    }
    __syncthreads();

    if (tid < NG * Cc) {                 // 255 threads: (j, c)
        int j = tid / Cc, c = tid % Cc;
        int m = g_mask[(b * NG + j) * Cc + c];
        atomicAdd(&s_kp[j], (float)m);
        if (m) {
            const float* pp = po + ((size_t)((b * Nc + i) * Cc + c)) * 2;
            const float* gp = go + ((size_t)((b * NG + j) * Cc + c)) * 2;
            float s0 = __fdividef(1.0f, 1.0f + __expf(-pp[0]));
            float s1 = __fdividef(1.0f, 1.0f + __expf(-pp[1]));
            float d0 = s0 - gp[0], d1 = s1 - gp[1];
            atomicAdd(&s_off[j], d0 * d0 + d1 * d1);
        }
    }
    __syncthreads();

    if (tid < NG) {
        int j = tid;
        float kp = fmaxf(s_kp[j], 1.0f);
        float hm = g_acc[(b * Nc + i) * NG + j] / kp;
        out[(b * Nc + i) * NG + j] = 2.0f * hm + s_score + s_off[j] / kp * 0.5f;
    }
}

// ---------------------------------------------------------------------------
extern "C" void kernel_launch(void* const* d_in, const int* in_sizes, int n_in,
                              void* d_out, int out_size) {
    const float* ph = (const float*)d_in[0];
    const float* ps = (const float*)d_in[1];
    const float* po = (const float*)d_in[2];
    const float* gh = (const float*)d_in[3];
    const float* go = (const float*)d_in[4];
    float* out = (float*)d_out;

    cudaFuncSetAttribute(gemm_kernel,
                         cudaFuncAttributeMaxDynamicSharedMemorySize,
                         (int)SMEM_BYTES);

    mask_kernel<<<dim3(Cc, NG, Bc), 128>>>(gh);
    gemm_kernel<<<dim3(HWc / KCHUNK, Cc, Bc), THREADS, SMEM_BYTES>>>(ph, gh);
    finalize_kernel<<<dim3(Nc, Bc), 256>>>(ps, po, go, out);
}